// round 5
// baseline (speedup 1.0000x reference)
#include <cuda_runtime.h>
#include <cstdint>

// ROI pooling (bilinear, half-pixel centers, clamped to crop).
//   img:  (1, 1024, 1024, 256) float32, NHWC
//   rois: (1, 300, 4) float32 (x0, y0, w, h) -> int
//   out:  (1, 300, 7, 7, 256) float32
//
// R5: bypass the per-SM L1tex wavefront queue (~248 wavefronts, the invariant
// that pinned R1-R4 at 11.0us) by fetching corner rows via cp.async.bulk
// (TMA path, mbarrier-tracked). One block = (roi, px): threads 0..27 each
// issue one 1KB bulk copy (7 py x 2 ycorner x 2 xcorner), everyone waits on
// one mbarrier, then lerps from smem.

#define POOL 7
#define IMG_W 1024
#define CCH 256
#define C4 64
#define NROWS 28                       // 7 py * 2 ycorner * 2 xcorner
#define ROW_BYTES (CCH * 4)            // 1024
#define TOTAL_TX (NROWS * ROW_BYTES)   // 28672

__global__ __launch_bounds__(256) void roi_pool_kernel(
    const float* __restrict__ img,     // (H*W*C) floats
    const float4* __restrict__ rois4,  // (300)
    float4* __restrict__ out4)         // (300*49, 64) float4
{
    __shared__ __align__(16) float4 buf[NROWS][C4];   // 28 KB
    __shared__ __align__(8) uint64_t mbar;

    const int roi = blockIdx.y;
    const int px  = blockIdx.x;            // 0..6
    const int ty  = threadIdx.y;           // 0..3
    const int c   = threadIdx.x;           // 0..63
    const int tid = ty * 64 + c;

    const float4 rp = __ldg(rois4 + roi);
    const int x0 = (int)rp.x;
    const int y0 = (int)rp.y;
    const int w  = (int)rp.z;
    const int h  = (int)rp.w;

    // x corner coords (shared by whole block)
    float cx = ((float)px + 0.5f) * ((float)w / (float)POOL) - 0.5f;
    cx = fminf(fmaxf(cx, 0.0f), (float)w - 1.0f);
    const int xlo = (int)cx;
    const int xhi = min(xlo + 1, w - 1);
    const float fx = cx - (float)xlo;

    const float hs   = (float)h / (float)POOL;
    const float hmax = (float)h - 1.0f;

    const uint32_t mb = (uint32_t)__cvta_generic_to_shared(&mbar);

    if (tid == 0) {
        asm volatile("mbarrier.init.shared.b64 [%0], %1;" :: "r"(mb), "r"(1u));
        asm volatile("mbarrier.arrive.expect_tx.shared.b64 _, [%0], %1;"
                     :: "r"(mb), "r"((uint32_t)TOTAL_TX) : "memory");
    }
    __syncthreads();   // mbar init + expect_tx visible before any copy lands

    if (tid < NROWS) {
        const int py = tid >> 2;           // 0..6
        const int yc = (tid >> 1) & 1;     // 0 = ylo, 1 = yhi
        const int xc = tid & 1;            // 0 = xlo, 1 = xhi

        float cy = ((float)py + 0.5f) * hs - 0.5f;
        cy = fminf(fmaxf(cy, 0.0f), hmax);
        const int ylo = (int)cy;
        const int yy  = yc ? min(ylo + 1, h - 1) : ylo;
        const int xx  = xc ? xhi : xlo;

        const float* gsrc = img + ((size_t)(y0 + yy) * IMG_W + (size_t)(x0 + xx)) * CCH;
        const uint32_t sdst = (uint32_t)__cvta_generic_to_shared(&buf[tid][0]);
        asm volatile(
            "cp.async.bulk.shared::cta.global.mbarrier::complete_tx::bytes "
            "[%0], [%1], %2, [%3];"
            :: "r"(sdst), "l"(gsrc), "r"((uint32_t)ROW_BYTES), "r"(mb)
            : "memory");
    }

    // Wait for all 28 KB
    {
        uint32_t done;
        asm volatile(
            "{\n\t.reg .pred p;\n\t"
            "mbarrier.try_wait.parity.shared.b64 p, [%1], %2;\n\t"
            "selp.b32 %0, 1, 0, p;\n\t}"
            : "=r"(done) : "r"(mb), "r"(0u) : "memory");
        while (!done) {
            asm volatile(
                "{\n\t.reg .pred p;\n\t"
                "mbarrier.try_wait.parity.shared.b64 p, [%1], %2;\n\t"
                "selp.b32 %0, 1, 0, p;\n\t}"
                : "=r"(done) : "r"(mb), "r"(0u) : "memory");
        }
    }

    const float gx = 1.0f - fx;
    const unsigned obase = (unsigned)roi * (POOL * POOL) * C4 + c;

    #pragma unroll
    for (int rep = 0; rep < 2; rep++) {
        const int py = ty + rep * 4;
        if (py >= POOL) break;

        float cy = ((float)py + 0.5f) * hs - 0.5f;
        cy = fminf(fmaxf(cy, 0.0f), hmax);
        const float fy = cy - floorf(cy);

        const float4 v00 = buf[py * 4 + 0][c];  // (ylo, xlo)
        const float4 v01 = buf[py * 4 + 1][c];  // (ylo, xhi)
        const float4 v10 = buf[py * 4 + 2][c];  // (yhi, xlo)
        const float4 v11 = buf[py * 4 + 3][c];  // (yhi, xhi)

        const float w00 = (1.0f - fy) * gx, w01 = (1.0f - fy) * fx;
        const float w10 = fy * gx,          w11 = fy * fx;
        float4 o;
        o.x = v00.x * w00 + v01.x * w01 + v10.x * w10 + v11.x * w11;
        o.y = v00.y * w00 + v01.y * w01 + v10.y * w10 + v11.y * w11;
        o.z = v00.z * w00 + v01.z * w01 + v10.z * w10 + v11.z * w11;
        o.w = v00.w * w00 + v01.w * w01 + v10.w * w10 + v11.w * w11;
        __stcs(out4 + obase + (unsigned)(py * POOL + px) * C4, o);
    }
}

extern "C" void kernel_launch(void* const* d_in, const int* in_sizes, int n_in,
                              void* d_out, int out_size)
{
    const float*  img   = (const float*)d_in[0];
    const float4* rois4 = (const float4*)d_in[1];
    float4* o4 = (float4*)d_out;

    dim3 block(64, 4, 1);
    dim3 grid(POOL, 300, 1);    // px x roi
    roi_pool_kernel<<<grid, block>>>(img, rois4, o4);
}

// round 7
// speedup vs baseline: 1.0351x; 1.0351x over previous
#include <cuda_runtime.h>
#include <cstdint>

// ROI pooling (bilinear, half-pixel centers, clamped to crop).
//   img:  (1, 1024, 1024, 256) float32, NHWC
//   rois: (1, 300, 4) float32 (x0, y0, w, h) -> int
//   out:  (1, 300, 7, 7, 256) float32
//
// R7 (= R6 fixed): sm_103a requires 32B-wide loads for L2::evict_last.
// Image reads: ld.global.nc.L2::evict_last.v4.b64 (keep 59MB read set L2-
// resident across graph replays). Output: st.global.cs.v4.b64 (evict-first
// streaming). 32 lanes x 32B cover each 1KB channel row.

#define POOL 7
#define IMG_W 1024
#define CF 256          // channels (floats)

struct F8 { float2 a0, a1, a2, a3; };   // 8 floats = 32B

__device__ __forceinline__ F8 ldg_keep32(const float* p) {
    uint64_t u0, u1, u2, u3;
    asm volatile("ld.global.nc.L2::evict_last.v4.b64 {%0,%1,%2,%3}, [%4];"
                 : "=l"(u0), "=l"(u1), "=l"(u2), "=l"(u3) : "l"(p));
    F8 r;
    r.a0 = *reinterpret_cast<float2*>(&u0);
    r.a1 = *reinterpret_cast<float2*>(&u1);
    r.a2 = *reinterpret_cast<float2*>(&u2);
    r.a3 = *reinterpret_cast<float2*>(&u3);
    return r;
}

__device__ __forceinline__ void stg_stream32(float* p, const float* v) {
    const uint64_t* u = reinterpret_cast<const uint64_t*>(v);
    asm volatile("st.global.cs.v4.b64 [%0], {%1,%2,%3,%4};"
                 :: "l"(p), "l"(u[0]), "l"(u[1]), "l"(u[2]), "l"(u[3])
                 : "memory");
}

__global__ __launch_bounds__(256) void roi_pool_kernel(
    const float*  __restrict__ img,    // (H*W*256) floats
    const float4* __restrict__ rois4,  // (300) float4 = (x0,y0,w,h)
    float*        __restrict__ out)    // (300*49*256) floats
{
    const int roi = blockIdx.y;
    const int pos = blockIdx.x * 8 + threadIdx.y;   // 0..55 (49.. skipped)
    if (pos >= POOL * POOL) return;
    const int py = pos / POOL;
    const int px = pos - py * POOL;

    const float4 rp = __ldg(rois4 + roi);
    const int x0 = (int)rp.x;
    const int y0 = (int)rp.y;
    const int w  = (int)rp.z;
    const int h  = (int)rp.w;

    // Sample coords, exactly as reference: c = (i+0.5)*(size/P) - 0.5, clamped.
    float cy = ((float)py + 0.5f) * ((float)h / (float)POOL) - 0.5f;
    cy = fminf(fmaxf(cy, 0.0f), (float)h - 1.0f);
    float cx = ((float)px + 0.5f) * ((float)w / (float)POOL) - 0.5f;
    cx = fminf(fmaxf(cx, 0.0f), (float)w - 1.0f);

    const int ylo = (int)cy;
    const int xlo = (int)cx;
    const int yhi = min(ylo + 1, h - 1);
    const int xhi = min(xlo + 1, w - 1);
    const float fy = cy - (float)ylo;
    const float fx = cx - (float)xlo;

    const float w00 = (1.0f - fy) * (1.0f - fx);
    const float w01 = (1.0f - fy) * fx;
    const float w10 = fy * (1.0f - fx);
    const float w11 = fy * fx;

    // Byte offsets fit in 32 bits (img = 2^28 floats).
    const unsigned r_lo = (unsigned)(y0 + ylo) * (IMG_W * CF);
    const unsigned r_hi = (unsigned)(y0 + yhi) * (IMG_W * CF);
    const unsigned cL   = (unsigned)(x0 + xlo) * CF;
    const unsigned cR   = (unsigned)(x0 + xhi) * CF;

    const unsigned c8 = (unsigned)threadIdx.x * 8;   // 0,8,..,248

    const F8 v00 = ldg_keep32(img + r_lo + cL + c8);
    const F8 v01 = ldg_keep32(img + r_lo + cR + c8);
    const F8 v10 = ldg_keep32(img + r_hi + cL + c8);
    const F8 v11 = ldg_keep32(img + r_hi + cR + c8);

    float o[8];
    const float* p00 = &v00.a0.x;
    const float* p01 = &v01.a0.x;
    const float* p10 = &v10.a0.x;
    const float* p11 = &v11.a0.x;
    #pragma unroll
    for (int i = 0; i < 8; i++)
        o[i] = p00[i] * w00 + p01[i] * w01 + p10[i] * w10 + p11[i] * w11;

    stg_stream32(out + ((unsigned)roi * (POOL * POOL) + pos) * CF + c8, o);
}

extern "C" void kernel_launch(void* const* d_in, const int* in_sizes, int n_in,
                              void* d_out, int out_size)
{
    const float*  img   = (const float*)d_in[0];
    const float4* rois4 = (const float4*)d_in[1];
    float* o = (float*)d_out;

    dim3 block(32, 8, 1);                      // 32 lanes x 8 pool positions
    dim3 grid((POOL * POOL + 7) / 8, 300, 1);  // 7 x 300
    roi_pool_kernel<<<grid, block>>>(img, rois4, o);
}

// round 8
// speedup vs baseline: 1.0536x; 1.0179x over previous
#include <cuda_runtime.h>
#include <cstdint>

// ROI pooling (bilinear, half-pixel centers, clamped to crop).
//   img:  (1, 1024, 1024, 256) float32, NHWC
//   rois: (1, 300, 4) float32 (x0, y0, w, h) -> int
//   out:  (1, 300, 7, 7, 256) float32
//
// R8: roofline-final polish. Seven prior variants all sit at 10.9-11.3us
// because total traffic (~75MB: 60MB irreducible corner reads + 15MB out)
// saturates the memory system at ~6.9TB/s. This version: exact-fit 224-thread
// blocks (zero wasted warps), 32-bit addressing, evict_last reads (keep read
// set L2-resident), DEFAULT-policy stores (write-back: output lines rewritten
// each graph replay stay dirty in L2 -> avoids 15MB/replay DRAM writeback
// that .cs eviction forces).

#define POOL 7
#define IMG_W 1024
#define CF 256          // channels (floats)

struct F8 { float f[8]; };   // 32 bytes

__device__ __forceinline__ F8 ldg_keep32(const float* p) {
    uint64_t u0, u1, u2, u3;
    asm volatile("ld.global.nc.L2::evict_last.v4.b64 {%0,%1,%2,%3}, [%4];"
                 : "=l"(u0), "=l"(u1), "=l"(u2), "=l"(u3) : "l"(p));
    F8 r;
    *reinterpret_cast<uint64_t*>(&r.f[0]) = u0;
    *reinterpret_cast<uint64_t*>(&r.f[2]) = u1;
    *reinterpret_cast<uint64_t*>(&r.f[4]) = u2;
    *reinterpret_cast<uint64_t*>(&r.f[6]) = u3;
    return r;
}

__device__ __forceinline__ void stg32(float* p, const float* v) {
    const uint64_t* u = reinterpret_cast<const uint64_t*>(v);
    asm volatile("st.global.v4.b64 [%0], {%1,%2,%3,%4};"
                 :: "l"(p), "l"(u[0]), "l"(u[1]), "l"(u[2]), "l"(u[3])
                 : "memory");
}

__global__ __launch_bounds__(224) void roi_pool_kernel(
    const float*  __restrict__ img,    // (H*W*256) floats
    const float4* __restrict__ rois4,  // (300) float4 = (x0,y0,w,h)
    float*        __restrict__ out)    // (300*49*256) floats
{
    const int roi = blockIdx.y;
    const int px  = blockIdx.x;      // 0..6
    const int py  = threadIdx.y;     // 0..6 (one warp per pool row)

    const float4 rp = __ldg(rois4 + roi);
    const int x0 = (int)rp.x;
    const int y0 = (int)rp.y;
    const int w  = (int)rp.z;
    const int h  = (int)rp.w;

    // Sample coords, exactly as reference: c = (i+0.5)*(size/P) - 0.5, clamped.
    float cy = ((float)py + 0.5f) * ((float)h / (float)POOL) - 0.5f;
    cy = fminf(fmaxf(cy, 0.0f), (float)h - 1.0f);
    float cx = ((float)px + 0.5f) * ((float)w / (float)POOL) - 0.5f;
    cx = fminf(fmaxf(cx, 0.0f), (float)w - 1.0f);

    const int ylo = (int)cy;
    const int xlo = (int)cx;
    const int yhi = min(ylo + 1, h - 1);
    const int xhi = min(xlo + 1, w - 1);
    const float fy = cy - (float)ylo;
    const float fx = cx - (float)xlo;

    const float w00 = (1.0f - fy) * (1.0f - fx);
    const float w01 = (1.0f - fy) * fx;
    const float w10 = fy * (1.0f - fx);
    const float w11 = fy * fx;

    // Float offsets fit in 32 bits (img = 2^28 floats).
    const unsigned r_lo = (unsigned)(y0 + ylo) * (IMG_W * CF);
    const unsigned r_hi = (unsigned)(y0 + yhi) * (IMG_W * CF);
    const unsigned cL   = (unsigned)(x0 + xlo) * CF;
    const unsigned cR   = (unsigned)(x0 + xhi) * CF;

    const unsigned c8 = (unsigned)threadIdx.x * 8;   // lane * 8 floats (32B)

    const F8 v00 = ldg_keep32(img + r_lo + cL + c8);
    const F8 v01 = ldg_keep32(img + r_lo + cR + c8);
    const F8 v10 = ldg_keep32(img + r_hi + cL + c8);
    const F8 v11 = ldg_keep32(img + r_hi + cR + c8);

    float o[8];
    #pragma unroll
    for (int i = 0; i < 8; i++)
        o[i] = v00.f[i] * w00 + v01.f[i] * w01 + v10.f[i] * w10 + v11.f[i] * w11;

    stg32(out + ((unsigned)roi * (POOL * POOL) + (unsigned)(py * POOL + px)) * CF + c8, o);
}

extern "C" void kernel_launch(void* const* d_in, const int* in_sizes, int n_in,
                              void* d_out, int out_size)
{
    const float*  img   = (const float*)d_in[0];
    const float4* rois4 = (const float4*)d_in[1];
    float* o = (float*)d_out;

    dim3 block(32, POOL, 1);    // 32 lanes x 7 pool rows = 224 (exact fit)
    dim3 grid(POOL, 300, 1);    // px x roi
    roi_pool_kernel<<<grid, block>>>(img, rois4, o);
}